// round 1
// baseline (speedup 1.0000x reference)
#include <cuda_runtime.h>

typedef unsigned long long ull;

#define ROWS_PER_CTA 32
#define RPW 4
#define NTHREADS 256
#define SMEM_BYTES 130112
#define GRID 1024   /* 32768 rows / 32 */

// ---------------- device-global precomputed tables ----------------
__device__ float g_Wc[64 * 1536];   // [f][n][k]  = sum_h Wp[f, n*64+h] * W[h,k]
__device__ float g_u[64 * 48];      // [f][n], [f][24+n] = Wc[f,n,:]·a1 , Wc[f,n,:]·a2
__device__ float g_v[48];           // v1[n]=bc[n,:]·a1, v2[n]=bc[n,:]·a2
__device__ float g_bc[24 * 64];     // bc[n,k] = sum_h bp[n*64+h] * W[h,k]

// ---------------- helpers ----------------
__device__ __forceinline__ ull packdup(float v) {
    ull r; asm("mov.b64 %0, {%1, %1};" : "=l"(r) : "f"(v)); return r;
}
#define FMA2(d, a_, b_, c_) \
    asm("fma.rn.f32x2 %0, %1, %2, %3;" : "=l"(d) : "l"(a_), "l"(b_), "l"(c_))

__device__ __forceinline__ void cp16(unsigned smaddr, const void* g) {
    asm volatile("cp.async.cg.shared.global [%0], [%1], 16;" :: "r"(smaddr), "l"(g));
}

// ---------------- prep kernel 1: Wc and u ----------------
__global__ void prep_wc(const float* __restrict__ Wp, const float* __restrict__ W,
                        const float* __restrict__ a) {
    int b = blockIdx.x;           // 0..1535
    int n = b >> 6;               // 0..23
    int f = b & 63;               // 0..63
    int k = threadIdx.x;          // 0..63
    float acc = 0.f;
#pragma unroll 8
    for (int h = 0; h < 64; h++)
        acc = fmaf(Wp[f * 1536 + n * 64 + h], W[h * 64 + k], acc);
    g_Wc[f * 1536 + n * 64 + k] = acc;

    float p1 = acc * a[k];
    float p2 = acc * a[64 + k];
#pragma unroll
    for (int d = 16; d; d >>= 1) {
        p1 += __shfl_xor_sync(0xffffffffu, p1, d);
        p2 += __shfl_xor_sync(0xffffffffu, p2, d);
    }
    __shared__ float r1[2], r2[2];
    if ((k & 31) == 0) { r1[k >> 5] = p1; r2[k >> 5] = p2; }
    __syncthreads();
    if (k == 0) {
        g_u[f * 48 + n]      = r1[0] + r1[1];
        g_u[f * 48 + 24 + n] = r2[0] + r2[1];
    }
}

// ---------------- prep kernel 2: bc and v ----------------
__global__ void prep_bc(const float* __restrict__ bp, const float* __restrict__ W,
                        const float* __restrict__ a) {
    int n = blockIdx.x;           // 0..23
    int k = threadIdx.x;          // 0..63
    float acc = 0.f;
#pragma unroll 8
    for (int h = 0; h < 64; h++)
        acc = fmaf(bp[n * 64 + h], W[h * 64 + k], acc);
    g_bc[n * 64 + k] = acc;

    float p1 = acc * a[k];
    float p2 = acc * a[64 + k];
#pragma unroll
    for (int d = 16; d; d >>= 1) {
        p1 += __shfl_xor_sync(0xffffffffu, p1, d);
        p2 += __shfl_xor_sync(0xffffffffu, p2, d);
    }
    __shared__ float r1[2], r2[2];
    if ((k & 31) == 0) { r1[k >> 5] = p1; r2[k >> 5] = p2; }
    __syncthreads();
    if (k == 0) { g_v[n] = r1[0] + r1[1]; g_v[24 + n] = r2[0] + r2[1]; }
}

// ---------------- main fused kernel ----------------
// shared layout (bytes):
//   [0,       98304)  s_wc : double buffer, 2 x (8 f-rows x 1536) floats
//   [98304,  115200)  s_xd : 64 x 33 ull, {x,x} duplicated pairs, [f][localrow]
//   [115200, 127616)  s_u  : 3072 floats (+pad)
//   [127616, 127808)  s_v  : 48 floats
//   [127808, 130112)  s_adj: 576 ints
__global__ __launch_bounds__(NTHREADS, 1)
void gat_main(const float* __restrict__ x, const int* __restrict__ adj,
              float* __restrict__ out) {
    extern __shared__ char smem[];
    float* s_wc  = (float*)smem;
    ull*   s_xd  = (ull*)(smem + 98304);
    float* s_u   = (float*)(smem + 115200);
    float* s_v   = (float*)(smem + 127616);
    int*   s_adj = (int*)(smem + 127808);

    const int tid  = threadIdx.x;
    const int lane = tid & 31;
    const int w    = tid >> 5;
    const int rowbase = blockIdx.x * ROWS_PER_CTA;

    const unsigned swc0 = (unsigned)__cvta_generic_to_shared(s_wc);

    // prologue: stage f-block 0 of Wc (48 KB) into buffer 0
    {
        const float* src = g_Wc;
        for (int c = tid; c < 3072; c += NTHREADS) cp16(swc0 + c * 16, src + c * 4);
        asm volatile("cp.async.commit_group;");
    }

    // stage x as duplicated {x,x} pairs: s_xd[f*33 + r]
    for (int i = tid; i < ROWS_PER_CTA * 64; i += NTHREADS) {
        int r = i >> 6, f = i & 63;
        s_xd[f * 33 + r] = packdup(x[(rowbase + r) * 64 + f]);
    }
    for (int i = tid; i < 3072; i += NTHREADS) s_u[i] = g_u[i];
    if (tid < 48) s_v[tid] = g_v[tid];
    for (int i = tid; i < 576; i += NTHREADS) s_adj[i] = adj[i];

    // Wh accumulators: lane owns columns k = 2*lane, 2*lane+1, for 4 rows x 24 nodes
    ull wh[RPW][24];
#pragma unroll
    for (int n = 0; n < 24; n++) {
        ull b = ((const ull*)g_bc)[n * 32 + lane];
        wh[0][n] = b; wh[1][n] = b; wh[2][n] = b; wh[3][n] = b;
    }

    __syncthreads();

    // ---------------- phase 1: Wh = x @ Wc + bc ----------------
    for (int fb = 0; fb < 8; fb++) {
        if (fb < 7) {
            unsigned dst = swc0 + (unsigned)(((fb + 1) & 1) * 49152);
            const float* src = g_Wc + (fb + 1) * 12288;
            for (int c = tid; c < 3072; c += NTHREADS) cp16(dst + c * 16, src + c * 4);
            asm volatile("cp.async.commit_group;");
            asm volatile("cp.async.wait_group 1;");
        } else {
            asm volatile("cp.async.wait_group 0;");
        }
        __syncthreads();

        const float* wct = s_wc + (fb & 1) * 12288;
#pragma unroll
        for (int ff = 0; ff < 8; ff++) {
            const int f = fb * 8 + ff;
            const ull* xp = s_xd + f * 33 + 4 * w;      // broadcast reads
            ull x0 = xp[0], x1 = xp[1], x2 = xp[2], x3 = xp[3];
            const ull* wrow = ((const ull*)(wct + ff * 1536)) + lane;
#pragma unroll
            for (int n = 0; n < 24; n++) {
                ull w2 = wrow[n * 32];
                FMA2(wh[0][n], w2, x0, wh[0][n]);
                FMA2(wh[1][n], w2, x1, wh[1][n]);
                FMA2(wh[2][n], w2, x2, wh[2][n]);
                FMA2(wh[3][n], w2, x3, wh[3][n]);
            }
        }
        __syncthreads();
    }

    // ---------------- phase 2: attention + aggregate per row ----------------
    const float* xdf = (const float*)s_xd;   // float view of duplicated pairs
    const int ln = (lane < 24) ? lane : 0;
    const float inv24 = 1.0f / 24.0f;

#pragma unroll
    for (int r = 0; r < RPW; r++) {
        const int rl  = 4 * w + r;
        const int row = rowbase + rl;

        // f1[n] = x·u1[:,n] + v1[n] ;  f2[n] = x·u2[:,n] + v2[n]   (lane = n for n<24)
        float f1 = s_v[ln], f2 = s_v[24 + ln];
        for (int f = 0; f < 64; f++) {
            float xf = xdf[2 * (f * 33 + rl)];           // broadcast
            f1 = fmaf(xf, s_u[f * 48 + ln], f1);
            f2 = fmaf(xf, s_u[f * 48 + 24 + ln], f2);
        }

        float acc0 = 0.f, acc1 = 0.f;
        for (int i = 0; i < 24; i++) {
            float f1i = __shfl_sync(0xffffffffu, f1, i);
            float e = f1i + f2;                          // lane j = lane
            e = (e > 0.f) ? e : 0.2f * e;                // LeakyReLU
            bool on = (lane < 24) && (s_adj[i * 24 + ln] > 0);
            e = on ? e : ((lane < 24) ? -9.0e15f : -__int_as_float(0x7f800000));
            // max reduce
            float m = e;
#pragma unroll
            for (int d = 16; d; d >>= 1) m = fmaxf(m, __shfl_xor_sync(0xffffffffu, m, d));
            float p = __expf(e - m);                     // pad lanes -> 0
            float s = p;
#pragma unroll
            for (int d = 16; d; d >>= 1) s += __shfl_xor_sync(0xffffffffu, s, d);
            float rs = __fdividef(1.0f, s);

            // h'[i, 2l..2l+1] = sum_j attn[i,j] * Wh[j, 2l..2l+1]
            ull hp = 0ULL;
#pragma unroll
            for (int j = 0; j < 24; j++) {
                float aj = __shfl_sync(0xffffffffu, p, j);
                ull a2 = packdup(aj);
                FMA2(hp, a2, wh[r][j], hp);
            }
            float hx = __uint_as_float((unsigned)hp) * rs;
            float hy = __uint_as_float((unsigned)(hp >> 32)) * rs;
            acc0 += (hx > 0.f) ? hx : expm1f(hx);        // ELU + mean accumulation
            acc1 += (hy > 0.f) ? hy : expm1f(hy);
        }

        float2 o; o.x = acc0 * inv24; o.y = acc1 * inv24;
        ((float2*)out)[row * 32 + lane] = o;
    }
}

// ---------------- launch ----------------
extern "C" void kernel_launch(void* const* d_in, const int* in_sizes, int n_in,
                              void* d_out, int out_size) {
    (void)in_sizes; (void)n_in; (void)out_size;
    const float* x   = (const float*)d_in[0];
    const int*   adj = (const int*)d_in[1];
    const float* Wp  = (const float*)d_in[2];
    const float* bp  = (const float*)d_in[3];
    const float* W   = (const float*)d_in[4];
    const float* a   = (const float*)d_in[5];
    float* out = (float*)d_out;

    cudaFuncSetAttribute(gat_main, cudaFuncAttributeMaxDynamicSharedMemorySize,
                         SMEM_BYTES);

    prep_wc<<<1536, 64>>>(Wp, W, a);
    prep_bc<<<24, 64>>>(bp, W, a);
    gat_main<<<GRID, NTHREADS, SMEM_BYTES>>>(x, adj, out);
}

// round 2
// speedup vs baseline: 1.4257x; 1.4257x over previous
#include <cuda_runtime.h>

typedef unsigned long long ull;

#define ROWS_PER_CTA 32
#define RPW 4
#define NTHREADS 256
#define GRID 1024   /* 32768 rows / 32 */

// shared layout (bytes)
#define OFF_XD   98304                    // after 2x48KB Wc double buffer
#define OFF_U    (OFF_XD + 64*34*8)       // 115712
#define OFF_V    (OFF_U + 3072*4)         // 128000
#define OFF_ADJJ (OFF_V + 192)            // 128192
#define OFF_RS   (OFF_ADJJ + 96)          // 128288
#define SMEM_BYTES (OFF_RS + 768 + 32)    // 129088

// ---------------- device-global precomputed tables ----------------
__device__ float g_Wc[64 * 1536];   // [f][n][k]  = sum_h Wp[f, n*64+h] * W[h,k]
__device__ float g_u[64 * 48];      // [f][n], [f][24+n]
__device__ float g_v[48];
__device__ float g_bc[24 * 64];     // bc[n,k]

// ---------------- helpers ----------------
__device__ __forceinline__ ull packdup(float v) {
    ull r; asm("mov.b64 %0, {%1, %1};" : "=l"(r) : "f"(v)); return r;
}
#define FMA2(d, a_, b_, c_) \
    asm("fma.rn.f32x2 %0, %1, %2, %3;" : "=l"(d) : "l"(a_), "l"(b_), "l"(c_))
#define ADD2(d, a_, b_) \
    asm("add.rn.f32x2 %0, %1, %2;" : "=l"(d) : "l"(a_), "l"(b_))

__device__ __forceinline__ void cp16(unsigned smaddr, const void* g) {
    asm volatile("cp.async.cg.shared.global [%0], [%1], 16;" :: "r"(smaddr), "l"(g));
}

// ---------------- prep kernel 1: Wc and u ----------------
__global__ void prep_wc(const float* __restrict__ Wp, const float* __restrict__ W,
                        const float* __restrict__ a) {
    int b = blockIdx.x;           // 0..1535
    int n = b >> 6;               // 0..23
    int f = b & 63;               // 0..63
    int k = threadIdx.x;          // 0..63
    float acc = 0.f;
#pragma unroll 8
    for (int h = 0; h < 64; h++)
        acc = fmaf(Wp[f * 1536 + n * 64 + h], W[h * 64 + k], acc);
    g_Wc[f * 1536 + n * 64 + k] = acc;

    float p1 = acc * a[k];
    float p2 = acc * a[64 + k];
#pragma unroll
    for (int d = 16; d; d >>= 1) {
        p1 += __shfl_xor_sync(0xffffffffu, p1, d);
        p2 += __shfl_xor_sync(0xffffffffu, p2, d);
    }
    __shared__ float r1[2], r2[2];
    if ((k & 31) == 0) { r1[k >> 5] = p1; r2[k >> 5] = p2; }
    __syncthreads();
    if (k == 0) {
        g_u[f * 48 + n]      = r1[0] + r1[1];
        g_u[f * 48 + 24 + n] = r2[0] + r2[1];
    }
}

// ---------------- prep kernel 2: bc and v ----------------
__global__ void prep_bc(const float* __restrict__ bp, const float* __restrict__ W,
                        const float* __restrict__ a) {
    int n = blockIdx.x;           // 0..23
    int k = threadIdx.x;          // 0..63
    float acc = 0.f;
#pragma unroll 8
    for (int h = 0; h < 64; h++)
        acc = fmaf(bp[n * 64 + h], W[h * 64 + k], acc);
    g_bc[n * 64 + k] = acc;

    float p1 = acc * a[k];
    float p2 = acc * a[64 + k];
#pragma unroll
    for (int d = 16; d; d >>= 1) {
        p1 += __shfl_xor_sync(0xffffffffu, p1, d);
        p2 += __shfl_xor_sync(0xffffffffu, p2, d);
    }
    __shared__ float r1[2], r2[2];
    if ((k & 31) == 0) { r1[k >> 5] = p1; r2[k >> 5] = p2; }
    __syncthreads();
    if (k == 0) { g_v[n] = r1[0] + r1[1]; g_v[24 + n] = r2[0] + r2[1]; }
}

// ---------------- main fused kernel ----------------
__global__ __launch_bounds__(NTHREADS, 1)
void gat_main(const float* __restrict__ x, const int* __restrict__ adj,
              float* __restrict__ out) {
    extern __shared__ char smem[];
    float* s_wc   = (float*)smem;
    ull*   s_P    = (ull*)smem;                 // overlays Wc region in phase 2
    ull*   s_xd   = (ull*)(smem + OFF_XD);      // 64 x 34 ull, {x,x} pairs [f][row]
    float* s_u    = (float*)(smem + OFF_U);
    float* s_v    = (float*)(smem + OFF_V);
    unsigned* s_adjJ = (unsigned*)(smem + OFF_ADJJ);
    float* s_rs   = (float*)(smem + OFF_RS);    // 8 warps x 24

    const int tid  = threadIdx.x;
    const int lane = tid & 31;
    const int w    = tid >> 5;
    const int rowbase = blockIdx.x * ROWS_PER_CTA;

    const unsigned swc0 = (unsigned)__cvta_generic_to_shared(s_wc);

    // prologue: stage f-block 0 of Wc (48 KB) into buffer 0
    {
        const float* src = g_Wc;
        for (int c = tid; c < 3072; c += NTHREADS) cp16(swc0 + c * 16, src + c * 4);
        asm volatile("cp.async.commit_group;");
    }

    // stage x as duplicated {x,x} pairs: s_xd[f*34 + r] (stride 34 -> 16B align for r%4==0)
    for (int i = tid; i < ROWS_PER_CTA * 64; i += NTHREADS) {
        int r = i >> 6, f = i & 63;
        s_xd[f * 34 + r] = packdup(x[(rowbase + r) * 64 + f]);
    }
    for (int i = tid; i < 3072; i += NTHREADS) s_u[i] = g_u[i];
    if (tid < 48) s_v[tid] = g_v[tid];
    if (tid < 24) {
        unsigned b = 0;
        for (int i = 0; i < 24; i++) b |= (adj[i * 24 + tid] > 0 ? 1u : 0u) << i;
        s_adjJ[tid] = b;
    }

    // Wh accumulators: lane owns k = 2*lane, 2*lane+1, for 4 rows x 24 nodes
    ull wh[RPW][24];
#pragma unroll
    for (int n = 0; n < 24; n++) {
        ull b = ((const ull*)g_bc)[n * 32 + lane];
        wh[0][n] = b; wh[1][n] = b; wh[2][n] = b; wh[3][n] = b;
    }

    __syncthreads();

    // ---------------- phase 1: Wh = x @ Wc + bc ----------------
    for (int fb = 0; fb < 8; fb++) {
        if (fb < 7) {
            unsigned dst = swc0 + (unsigned)(((fb + 1) & 1) * 49152);
            const float* src = g_Wc + (fb + 1) * 12288;
            for (int c = tid; c < 3072; c += NTHREADS) cp16(dst + c * 16, src + c * 4);
            asm volatile("cp.async.commit_group;");
            asm volatile("cp.async.wait_group 1;");
        } else {
            asm volatile("cp.async.wait_group 0;");
        }
        __syncthreads();

        const float* wct = s_wc + (fb & 1) * 12288;
#pragma unroll
        for (int ff = 0; ff < 8; ff++) {
            const int f = fb * 8 + ff;
            const ulonglong2* xp = (const ulonglong2*)(s_xd + f * 34 + 4 * w);
            ulonglong2 xa = xp[0], xb = xp[1];
            ull x0 = xa.x, x1 = xa.y, x2 = xb.x, x3 = xb.y;
            const ull* wrow = ((const ull*)(wct + ff * 1536)) + lane;
            // chunk n into 4 x 6 to bound the live load window (anti-spill)
#pragma unroll
            for (int nc = 0; nc < 4; nc++) {
                ull w2[6];
#pragma unroll
                for (int q = 0; q < 6; q++) w2[q] = wrow[(nc * 6 + q) * 32];
#pragma unroll
                for (int q = 0; q < 6; q++) {
                    const int n = nc * 6 + q;
                    FMA2(wh[0][n], w2[q], x0, wh[0][n]);
                    FMA2(wh[1][n], w2[q], x1, wh[1][n]);
                    FMA2(wh[2][n], w2[q], x2, wh[2][n]);
                    FMA2(wh[3][n], w2[q], x3, wh[3][n]);
                }
                asm volatile("" ::: "memory");
            }
        }
        __syncthreads();
    }

    // ---------------- phase 2: attention + aggregate ----------------
    const int ln = (lane < 24) ? lane : 0;

    // f1/f2 for all 4 samples, lane = node n
    float f1[RPW], f2[RPW];
#pragma unroll
    for (int r = 0; r < RPW; r++) { f1[r] = s_v[ln]; f2[r] = s_v[24 + ln]; }
    for (int f = 0; f < 64; f++) {
        float u1 = s_u[f * 48 + ln];
        float u2 = s_u[f * 48 + 24 + ln];
        const float* xr = (const float*)(s_xd + f * 34 + 4 * w);
#pragma unroll
        for (int r = 0; r < RPW; r++) {
            float xf = xr[2 * r];                      // low half of {x,x}
            f1[r] = fmaf(xf, u1, f1[r]);
            f2[r] = fmaf(xf, u2, f2[r]);
        }
    }

    ull* Pw = s_P + w * 600;        // per-warp 24 x 25 ull scratch (4.8 KB)
    const float inv24 = 1.0f / 24.0f;

#pragma unroll
    for (int r = 0; r < RPW; r++) {
        // ---- stage A: unnormalized probs, lanes = i, loop j ----
        float sse = 0.f;
        const float f1v = f1[r], f2v = f2[r];
#pragma unroll 6
        for (int j = 0; j < 24; j++) {
            float f2j = __shfl_sync(0xffffffffu, f2v, j);
            float e = f1v + f2j;
            e = (e > 0.f) ? e : 0.2f * e;              // LeakyReLU
            unsigned bits = s_adjJ[j];                 // uniform
            float p = ((bits >> lane) & 1u) ? __expf(e) : 0.f;
            sse += p;
            if (lane < 24) Pw[lane * 25 + j] = packdup(p);
        }
        // rare: fully-masked row -> reference softmax is uniform
        bool bad = (lane < 24) && (sse == 0.f);
        if (__any_sync(0xffffffffu, bad)) {
            if (bad) {
                for (int j = 0; j < 24; j++) Pw[lane * 25 + j] = packdup(1.f);
                sse = 24.f;
            }
        }
        if (lane < 24) s_rs[w * 24 + lane] = __fdividef(1.f, sse);
        __syncwarp();

        // ---- stage B: h' = attn @ Wh, lanes = k-pair, loop i ----
        float acc0 = 0.f, acc1 = 0.f;
        for (int i = 0; i < 24; i++) {
            const ull* Prow = Pw + i * 25;
            ull hp0 = 0ULL, hp1 = 0ULL, hp2 = 0ULL;    // 3 chains for ILP
#pragma unroll
            for (int tc = 0; tc < 3; tc++) {
                ull pv[8];
#pragma unroll
                for (int q = 0; q < 8; q++) pv[q] = Prow[tc * 8 + q];
#pragma unroll
                for (int q = 0; q < 8; q++) {
                    if (tc == 0)      { FMA2(hp0, pv[q], wh[r][q],      hp0); }
                    else if (tc == 1) { FMA2(hp1, pv[q], wh[r][8 + q],  hp1); }
                    else              { FMA2(hp2, pv[q], wh[r][16 + q], hp2); }
                }
                asm volatile("" ::: "memory");
            }
            ull hps, hp;
            ADD2(hps, hp0, hp1);
            ADD2(hp, hps, hp2);
            float rsv = s_rs[w * 24 + i];              // uniform
            float hx = __uint_as_float((unsigned)hp) * rsv;
            float hy = __uint_as_float((unsigned)(hp >> 32)) * rsv;
            acc0 += (hx > 0.f) ? hx : __expf(hx) - 1.f;   // ELU
            acc1 += (hy > 0.f) ? hy : __expf(hy) - 1.f;
        }

        const int row = rowbase + 4 * w + r;
        float2 o; o.x = acc0 * inv24; o.y = acc1 * inv24;
        ((float2*)out)[row * 32 + lane] = o;
        __syncwarp();   // protect Pw before next sample overwrites
    }
}

// ---------------- launch ----------------
extern "C" void kernel_launch(void* const* d_in, const int* in_sizes, int n_in,
                              void* d_out, int out_size) {
    (void)in_sizes; (void)n_in; (void)out_size;
    const float* x   = (const float*)d_in[0];
    const int*   adj = (const int*)d_in[1];
    const float* Wp  = (const float*)d_in[2];
    const float* bp  = (const float*)d_in[3];
    const float* W   = (const float*)d_in[4];
    const float* a   = (const float*)d_in[5];
    float* out = (float*)d_out;

    cudaFuncSetAttribute(gat_main, cudaFuncAttributeMaxDynamicSharedMemorySize,
                         SMEM_BYTES);

    prep_wc<<<1536, 64>>>(Wp, W, a);
    prep_bc<<<24, 64>>>(bp, W, a);
    gat_main<<<GRID, NTHREADS, SMEM_BYTES>>>(x, adj, out);
}